// round 10
// baseline (speedup 1.0000x reference)
#include <cuda_runtime.h>
#include <cuda_fp16.h>
#include <cstdint>

#define BB 32
#define TT 512
#define KK 48
#define NTH 192
#define NB 6
#define EROWB 132                  // bytes per j-row of an E tile (33 words, bank-bijective)
#define ETILEB (KK * EROWB)        // 6336 B
#define ECH (ETILEB / 16)          // 396 16B chunks
#define FSROW 52                   // producer fp32 staging row stride (words)
#define START_TAG 46
#define STOP_TAG 47
#define BIGDONE (1 << 20)

// E tiles: gE[b][t] is 48 rows (j), 132 B each; row j, u-block u (0..3) at byte 32u
// holds 6 half2 = exp(f[i][j]) for i = 12u .. 12u+11.
__device__ __align__(128) char gE[(size_t)BB * TT * ETILEB];
__device__ float gGoldPart[BB][4];
__device__ int   gPos[BB][4];          // zero-init; tiles completed per producer
__device__ float g_partials[BB];
__device__ int   g_ctr = 0;

__device__ __forceinline__ float ex2f(float x) {
    float y; asm("ex2.approx.ftz.f32 %0, %1;" : "=f"(y) : "f"(x)); return y;
}
__device__ __forceinline__ float lg2f(float x) {
    float y; asm("lg2.approx.ftz.f32 %0, %1;" : "=f"(y) : "f"(x)); return y;
}
__device__ __forceinline__ void cp16(uint32_t smem, const void* g) {
    asm volatile("cp.async.cg.shared.global [%0], [%1], 16;" :: "r"(smem), "l"(g));
}
__device__ __forceinline__ void cp_commit() { asm volatile("cp.async.commit_group;"); }
__device__ __forceinline__ void cp_wait1()  { asm volatile("cp.async.wait_group 1;"); }
__device__ __forceinline__ void cp_wait3()  { asm volatile("cp.async.wait_group 3;"); }
__device__ __forceinline__ void cp_wait4()  { asm volatile("cp.async.wait_group 4;"); }
__device__ __forceinline__ int ld_acq(const int* p) {
    int v; asm volatile("ld.acquire.gpu.b32 %0, [%1];" : "=r"(v) : "l"(p)); return v;
}
__device__ __forceinline__ void st_rel(int* p, int v) {
    asm volatile("st.release.gpu.b32 [%0], %1;" :: "l"(p), "r"(v));
}

extern __shared__ char smem_dyn[];

__global__ __launch_bounds__(NTH, 1)
void crf_fused_kernel(const float* __restrict__ feat,
                      const int*   __restrict__ targets,
                      const int*   __restrict__ lengths,
                      float*       __restrict__ out)
{
    const int tid = threadIdx.x;
    const float LOG2E = 1.4426950408889634f;
    const float LN2   = 0.6931471805599453f;

    if (blockIdx.x >= BB) {
        // =========================== PRODUCER ===========================
        const int pid = blockIdx.x - BB;
        int b, q, nbp;
        if (pid < 80) { b = pid >> 2; q = pid & 3; nbp = 4; }
        else { int r = pid - 80; b = 20 + r / 3; q = r % 3; nbp = 3; }
        const int len = lengths[b];
        const float* fb = feat + (size_t)b * TT * (KK * KK);

        float* fstg = (float*)smem_dyn;               // 2 x KK*FSROW floats
        uint32_t sf[2];
        sf[0] = (uint32_t)__cvta_generic_to_shared(fstg);
        sf[1] = (uint32_t)__cvta_generic_to_shared(fstg + KK * FSROW);

        uint32_t pso[3]; size_t pgo[3];
        #pragma unroll
        for (int m = 0; m < 3; ++m) {
            int k = tid + m * NTH;                    // 576 chunks
            pso[m] = (uint32_t)((k / 12) * FSROW * 4 + (k % 12) * 16);
            pgo[m] = (size_t)(k / 12) * KK + (size_t)(k % 12) * 4;
        }
        const int jj = tid >> 2;                      // 0..47
        const int uu = tid & 3;                       // 0..3

        float gold = 0.f;
        if (q < len) {
            {   // issue first tile
                const float* src = fb + (size_t)q * (KK * KK);
                #pragma unroll
                for (int m = 0; m < 3; ++m) cp16(sf[0] + pso[m], src + pgo[m]);
                cp_commit();
            }
            int buf = 0, done = 0;
            for (int t = q; t < len; t += nbp) {
                int tn = t + nbp;
                if (tn < len) {
                    const float* src = fb + (size_t)tn * (KK * KK);
                    #pragma unroll
                    for (int m = 0; m < 3; ++m) cp16(sf[buf ^ 1] + pso[m], src + pgo[m]);
                }
                cp_commit();
                cp_wait1();                           // tile t complete
                __syncthreads();

                const float* F = fstg + buf * (KK * FSROW);
                char* dst = gE + (size_t)(b * TT + t) * ETILEB
                          + (size_t)jj * EROWB + 32 * uu;
                #pragma unroll
                for (int k = 0; k < 6; ++k) {
                    int i0 = 12 * uu + 2 * k;
                    float e0 = ex2f(F[i0 * FSROW + jj] * LOG2E);
                    float e1 = ex2f(F[(i0 + 1) * FSROW + jj] * LOG2E);
                    *(__half2*)(dst + 4 * k) = __floats2half2_rn(e0, e1);
                }
                if (tid == 0) {
                    int tg = targets[b * TT + t];
                    gold += F[(tg / KK) * FSROW + (tg % KK)];
                }
                __threadfence();
                __syncthreads();
                if (tid == 0) st_rel(&gPos[b][q], ++done);
                buf ^= 1;
            }
        }
        if (tid == 0) {
            gGoldPart[b][q] = gold;
            __threadfence();
            st_rel(&gPos[b][q], BIGDONE);
        }
    } else {
        // =========================== CONSUMER ===========================
        const int b   = blockIdx.x;
        const int len = lengths[b];
        const int nbq = (b < 20) ? 4 : 3;
        const char* gEb = gE + (size_t)b * TT * ETILEB;

        char*  ering = smem_dyn;                          // NB * ETILEB
        float* cbuf  = (float*)(smem_dyn + NB * ETILEB);  // 2 x 64 floats
        uint32_t sring = (uint32_t)__cvta_generic_to_shared(ering);

        const int l = tid & 31;
        const int w = tid >> 5;
        const int j = 8 * w + (l & 7);     // owned column
        const int u = l >> 3;              // i in [12u, 12u+12)

        int F = 0;                          // tiles < F are ready in gE
        // --- helpers (uniform across threads) ---
        auto ensure = [&](int tt) {
            if (F <= tt) {
                int mn;
                do {
                    mn = ld_acq(&gPos[b][0]);
                    #pragma unroll
                    for (int qq = 1; qq < 4; ++qq)
                        if (qq < nbq) { int v = ld_acq(&gPos[b][qq]); mn = v < mn ? v : mn; }
                } while (nbq * mn <= tt);
                F = nbq * mn;
            }
        };
        auto issue = [&](int tt, int slot) {
            uint32_t d = sring + slot * ETILEB;
            const char* s = gEb + (size_t)tt * ETILEB;
            cp16(d + tid * 16, s + (size_t)tid * 16);
            cp16(d + (tid + 192) * 16, s + (size_t)(tid + 192) * 16);
            if (tid < (ECH - 384)) cp16(d + (tid + 384) * 16, s + (size_t)(tid + 384) * 16);
        };

        // Prologue: tiles 0..4 as 5 groups
        #pragma unroll
        for (int tt = 0; tt < 5; ++tt) {
            if (tt < len) { ensure(tt); issue(tt, tt); }
            cp_commit();
        }
        cp_wait4();
        __syncthreads();                    // tile 0 visible

        // init carries c(0)[j] = exp(f0[46][j]) : row j, byte 116, low half
        if (tid < KK)
            cbuf[tid] = __half2float(*(const __half*)(ering + tid * EROWB + 116));
        int eacc = 0;

        cp_wait3();
        __syncthreads();                    // tile 1 visible

        float Ef[12];
        {
            const char* et = ering + 1 * ETILEB + j * EROWB + 32 * u;
            #pragma unroll
            for (int k = 0; k < 6; ++k) {
                float2 f2 = __half22float2(*(const __half2*)(et + 4 * k));
                Ef[2 * k] = f2.x; Ef[2 * k + 1] = f2.y;
            }
        }
        if (5 < len) { ensure(5); issue(5, 5); }
        cp_commit();

        int nxt = 2;    // (t+1) % NB
        int pfb = 0;    // (t+5) % NB
        for (int t = 1; t < len; ++t) {
            cp_wait3();
            __syncthreads();                // carries(t-1) + tile t+1 visible

            int tn = t + 5;
            if (tn < len) { ensure(tn); issue(tn, pfb); }
            cp_commit();

            const float* dr = cbuf + ((t - 1) & 1) * 64;
            const float  c0 = dr[0];
            const uint32_t cbits = __float_as_uint(c0);
            const int      be   = (int)(cbits >> 23);
            const float    rsc  = __uint_as_float((uint32_t)(254 - be) << 23);
            eacc += be - 127;

            float4 A = *(const float4*)(dr + 12 * u);
            float4 Bq = *(const float4*)(dr + 12 * u + 4);
            float4 Cq = *(const float4*)(dr + 12 * u + 8);

            float a0 = Ef[0] * A.x;
            float a1 = Ef[1] * A.y;
            a0 = fmaf(Ef[2],  A.z,  a0);
            a1 = fmaf(Ef[3],  A.w,  a1);
            a0 = fmaf(Ef[4],  Bq.x, a0);
            a1 = fmaf(Ef[5],  Bq.y, a1);
            a0 = fmaf(Ef[6],  Bq.z, a0);
            a1 = fmaf(Ef[7],  Bq.w, a1);
            a0 = fmaf(Ef[8],  Cq.x, a0);
            a1 = fmaf(Ef[9],  Cq.y, a1);
            a0 = fmaf(Ef[10], Cq.z, a0);
            a1 = fmaf(Ef[11], Cq.w, a1);
            float acc = a0 + a1;

            acc += __shfl_xor_sync(0xffffffffu, acc, 8);
            acc += __shfl_xor_sync(0xffffffffu, acc, 16);
            if (u == 0) cbuf[(t & 1) * 64 + j] = acc * rsc;

            // preload E(t+1) from slot nxt (dead at t = len-1, harmless)
            {
                const char* et = ering + nxt * ETILEB + j * EROWB + 32 * u;
                #pragma unroll
                for (int k = 0; k < 6; ++k) {
                    float2 f2 = __half22float2(*(const __half2*)(et + 4 * k));
                    Ef[2 * k] = f2.x; Ef[2 * k + 1] = f2.y;
                }
            }

            if (++nxt == NB) nxt = 0;
            if (++pfb == NB) pfb = 0;
        }

        __syncthreads();
        if (tid == 0) {
            // wait for producers' gold partials (this replay), fixed-order sum
            float gold = 0.f;
            for (int qq = 0; qq < nbq; ++qq) {
                while (ld_acq(&gPos[b][qq]) != BIGDONE) {}
                gold += gGoldPart[b][qq];
            }
            float fin = ((float)eacc + lg2f(cbuf[((len - 1) & 1) * 64 + STOP_TAG])) * LN2;
            g_partials[b] = fin - gold;
        }

        // fused deterministic batch reduction (last consumer)
        if (tid < 32) {
            int old = 0;
            if (tid == 0) {
                __threadfence();
                old = atomicAdd(&g_ctr, 1);
            }
            old = __shfl_sync(0xffffffffu, old, 0);
            if (old == BB - 1) {
                __threadfence();
                float v = g_partials[tid];
                #pragma unroll
                for (int o = 16; o; o >>= 1) v += __shfl_down_sync(0xffffffffu, v, o);
                if (tid == 0) { out[0] = v / (float)BB; g_ctr = 0; }
            }
        }
    }
}

extern "C" void kernel_launch(void* const* d_in, const int* in_sizes, int n_in,
                              void* d_out, int out_size)
{
    const float* feat    = (const float*)d_in[0];
    const int*   targets = (const int*)d_in[1];
    const int*   lengths = (const int*)d_in[2];
    float*       out     = (float*)d_out;

    // consumer smem (NB*ETILEB + carries) dominates producer staging
    const int smem_bytes = NB * ETILEB + 2 * 64 * 4 + 256;   // ~38.8 KB
    cudaFuncSetAttribute(crf_fused_kernel, cudaFuncAttributeMaxDynamicSharedMemorySize, smem_bytes);
    crf_fused_kernel<<<BB + 116, NTH, smem_bytes>>>(feat, targets, lengths, out);
}

// round 11
// speedup vs baseline: 1.5437x; 1.5437x over previous
#include <cuda_runtime.h>
#include <cuda_fp16.h>
#include <cstdint>

#define BB 32
#define TT 512
#define KK 48
#define SROW 56              // banks (24u + j) % 32 all distinct for u=0..3, j-span 8
#define TILESZ (KK * SROW)   // 2688
#define NTH 192              // 6 warps
#define NB 6
#define CARRYSZ 80           // slot for tag i = u + 4*ii : u*20 + ii
#define START_TAG 46
#define STOP_TAG 47

__device__ float g_partials[BB];
__device__ int   g_ctr = 0;

__device__ __forceinline__ float ex2f(float x) {
    float y; asm("ex2.approx.ftz.f32 %0, %1;" : "=f"(y) : "f"(x)); return y;
}
__device__ __forceinline__ float lg2f(float x) {
    float y; asm("lg2.approx.ftz.f32 %0, %1;" : "=f"(y) : "f"(x)); return y;
}
__device__ __forceinline__ void cp16(uint32_t smem, const void* g) {
    asm volatile("cp.async.cg.shared.global [%0], [%1], 16;" :: "r"(smem), "l"(g));
}
__device__ __forceinline__ void cp_commit() { asm volatile("cp.async.commit_group;"); }
__device__ __forceinline__ void cp_wait3()  { asm volatile("cp.async.wait_group 3;"); }
__device__ __forceinline__ void cp_wait4()  { asm volatile("cp.async.wait_group 4;"); }

// tag i = u + 4*ii  ->  slot u*20 + ii
__device__ __forceinline__ int pslot(int i) { return (i & 3) * 20 + (i >> 2); }

// packed-pair exp: E0,E1 = 2^f0, 2^f1 via one MUFU op (ex2.approx.f16x2)
__device__ __forceinline__ void ex2_pair(float f0, float f1, float& e0, float& e1) {
    uint32_t p, r;
    asm("cvt.rn.f16x2.f32 %0, %1, %2;" : "=r"(p) : "f"(f1), "f"(f0));  // hi=f1, lo=f0
    asm volatile("ex2.approx.f16x2 %0, %1;" : "=r"(r) : "r"(p));
    asm volatile("{.reg .f16 lo, hi;\n\t"
                 " mov.b32 {lo, hi}, %2;\n\t"
                 " cvt.f32.f16 %0, lo;\n\t"
                 " cvt.f32.f16 %1, hi;}"
                 : "=f"(e0), "=f"(e1) : "r"(r));
}

extern __shared__ float smem_dyn[];

__global__ __launch_bounds__(NTH, 1)
void crf_fwd_kernel(const float* __restrict__ feat,
                    const int*   __restrict__ targets,
                    const int*   __restrict__ lengths,
                    float*       __restrict__ out)
{
    float* tile = smem_dyn;                     // NB * TILESZ
    float* dshP = tile + NB * TILESZ;           // 2 * CARRYSZ
    int*   tsh  = (int*)(dshP + 2 * CARRYSZ);   // TT

    const int b   = blockIdx.x;
    const int tid = threadIdx.x;
    const int len = lengths[b];
    const float* fb = feat + (size_t)b * TT * (KK * KK);

    for (int i = tid; i < TT; i += NTH) {
        int v = targets[b * TT + i];
        tsh[i] = (v / KK) * SROW + (v % KK);
    }

    // warp w owns columns 8w..8w+7: j = 8w + (l&7); i = u + 4*ii, u = l>>3
    const int l = tid & 31;
    const int w = tid >> 5;
    const int j = 8 * w + (l & 7);
    const int u = l >> 3;

    // prefetch chunks: exactly 3 per thread (576 = 3*192)
    uint32_t so[3]; size_t go[3];
    #pragma unroll
    for (int q = 0; q < 3; ++q) {
        int k = tid + q * NTH;
        so[q] = (uint32_t)((k / 12) * SROW * 4 + (k % 12) * 16);
        go[q] = (size_t)(k / 12) * KK + (size_t)(k % 12) * 4;
    }

    uint32_t sb[NB];
    #pragma unroll
    for (int n = 0; n < NB; ++n)
        sb[n] = (uint32_t)__cvta_generic_to_shared(tile + n * TILESZ);

    const float LOG2E = 1.4426950408889634f;
    const float LN2   = 0.6931471805599453f;

    // Prologue: issue tiles 0..4 as 5 groups
    #pragma unroll
    for (int tt = 0; tt < 5; ++tt) {
        if (tt < len) {
            const float* src = fb + (size_t)tt * (KK * KK);
            #pragma unroll
            for (int q = 0; q < 3; ++q) cp16(sb[tt] + so[q], src + go[q]);
        }
        cp_commit();
    }
    cp_wait4();
    __syncthreads();       // tile 0 visible

    // init: raw linear carries S = 2^(f0[START,:]*log2e) (fp32 exp), buffer 1
    if (tid < KK) dshP[CARRYSZ + pslot(tid)] = ex2f(tile[SROW * START_TAG + tid] * LOG2E);
    float gold = 0.f;
    int   eacc = 0;
    if (tid == 0) gold = tile[tsh[0]];

    cp_wait3();
    __syncthreads();       // tile 1 visible

    // E for tile 1 (12 per lane, via 6 packed MUFU ops)
    float E[12];
    {
        const float* fn = tile + 1 * TILESZ + u * SROW + j;
        #pragma unroll
        for (int k = 0; k < 6; ++k) {
            float f0 = fn[SROW * 4 * (2 * k)]     * LOG2E;
            float f1 = fn[SROW * 4 * (2 * k + 1)] * LOG2E;
            ex2_pair(f0, f1, E[2 * k], E[2 * k + 1]);
        }
    }
    if (5 < len) {
        const float* src = fb + (size_t)5 * (KK * KK);
        #pragma unroll
        for (int q = 0; q < 3; ++q) cp16(sb[5] + so[q], src + go[q]);
    }
    cp_commit();

    int cur = 1;   // t % NB
    int pfb = 0;   // (t+5) % NB
    for (int t = 1; t < len; ++t) {
        cp_wait3();
        __syncthreads();     // carries(t) + tile t+1 visible; buffer pfb drained

        // prefetch tile t+5
        {
            int tn = t + 5;
            if (tn < len) {
                const float* src = fb + (size_t)tn * (KK * KK);
                uint32_t dst = sb[pfb];
                #pragma unroll
                for (int q = 0; q < 3; ++q) cp16(dst + so[q], src + go[q]);
            }
            cp_commit();
        }

        const float* dr = dshP + (t & 1) * CARRYSZ;
        const float  c0 = dr[0];
        // exact power-of-two renormalization: r = 2^-(ilogb(c0))
        const uint32_t cb = __float_as_uint(c0);
        const int      be = (int)(cb >> 23);
        const float    rsc = __uint_as_float((uint32_t)(254 - be) << 23);

        float4 A = *(const float4*)(dr + u * 20 + 0);
        float4 B = *(const float4*)(dr + u * 20 + 4);
        float4 C = *(const float4*)(dr + u * 20 + 8);

        float a0 = E[0] * A.x;
        float a1 = E[1] * A.y;
        a0 = fmaf(E[2],  A.z, a0);
        a1 = fmaf(E[3],  A.w, a1);
        a0 = fmaf(E[4],  B.x, a0);
        a1 = fmaf(E[5],  B.y, a1);
        a0 = fmaf(E[6],  B.z, a0);
        a1 = fmaf(E[7],  B.w, a1);
        a0 = fmaf(E[8],  C.x, a0);
        a1 = fmaf(E[9],  C.y, a1);
        a0 = fmaf(E[10], C.z, a0);
        a1 = fmaf(E[11], C.w, a1);
        float acc = a0 + a1;

        if (tid == 0) {
            eacc += be - 127;
            gold += tile[cur * TILESZ + tsh[t]];
        }

        // E for tile t+1 (pinned pre-barrier; dead at t = len-1, harmless)
        {
            const float* fn = tile + ((cur + 1 == NB) ? 0 : cur + 1) * TILESZ + u * SROW + j;
            #pragma unroll
            for (int k = 0; k < 6; ++k) {
                float f0 = fn[SROW * 4 * (2 * k)]     * LOG2E;
                float f1 = fn[SROW * 4 * (2 * k + 1)] * LOG2E;
                ex2_pair(f0, f1, E[2 * k], E[2 * k + 1]);
            }
        }

        acc += __shfl_xor_sync(0xffffffffu, acc, 8);
        acc += __shfl_xor_sync(0xffffffffu, acc, 16);
        if (u == 0) dshP[((t + 1) & 1) * CARRYSZ + pslot(j)] = acc * rsc;

        if (++cur == NB) cur = 0;
        if (++pfb == NB) pfb = 0;
    }

    __syncthreads();
    if (tid == 0) {
        float fin = ((float)eacc + lg2f(dshP[(len & 1) * CARRYSZ + pslot(STOP_TAG)])) * LN2;
        g_partials[b] = fin - gold;
    }

    // fused deterministic batch reduction (last block)
    if (tid < 32) {
        int old = 0;
        if (tid == 0) {
            __threadfence();
            old = atomicAdd(&g_ctr, 1);
        }
        old = __shfl_sync(0xffffffffu, old, 0);
        if (old == BB - 1) {
            __threadfence();
            float v = g_partials[tid];
            #pragma unroll
            for (int o = 16; o; o >>= 1) v += __shfl_down_sync(0xffffffffu, v, o);
            if (tid == 0) { out[0] = v / (float)BB; g_ctr = 0; }
        }
    }
}

extern "C" void kernel_launch(void* const* d_in, const int* in_sizes, int n_in,
                              void* d_out, int out_size)
{
    const float* feat    = (const float*)d_in[0];
    const int*   targets = (const int*)d_in[1];
    const int*   lengths = (const int*)d_in[2];
    float*       out     = (float*)d_out;

    const int smem_bytes = (NB * TILESZ + 2 * CARRYSZ) * 4 + TT * 4;  // ~67 KB
    cudaFuncSetAttribute(crf_fwd_kernel, cudaFuncAttributeMaxDynamicSharedMemorySize, smem_bytes);
    crf_fwd_kernel<<<BB, NTH, smem_bytes>>>(feat, targets, lengths, out);
}